// round 2
// baseline (speedup 1.0000x reference)
#include <cuda_runtime.h>
#include <cuda_bf16.h>

// ---------------------------------------------------------------------------
// Weight_Generation: conv3x3(3->16) + BatchNorm(train) + ReLU on [1024,3,32,32]
// plus hypernetwork generating 36 conv weight tensors from 242 z-vectors.
//
// Output layout (float32): [ 36 weight tensors concatenated = 242*2304 floats ]
//                          [ y : 1024*16*32*32 floats ]
// ---------------------------------------------------------------------------

#define Y_OFFSET   (242 * 2304)        // 557568
#define N_ELEM_PER_CH (1024.0f * 1024.0f)  // 1024 imgs * 1024 pix

// scratch (device globals; no allocations allowed)
__device__ float g_partials[1024 * 32];   // [block][ch(0..15)=sum, ch+16=sumsq]
__device__ float g_scale[16];
__device__ float g_shift[16];

// layer tables (36 layers)
__constant__ int c_offs[37] = {
    0,1,2,3,4,5,6,7,8,9,10,11,12,          // layers 0..11 (1x1)
    14,                                     // layer 12 (2x1)
    18,22,26,30,34,38,42,46,50,54,58,       // layers 13..23 (2x2)
    66,                                     // layer 24 (4x2)
    82,98,114,130,146,162,178,194,210,226,242 // layers 25..35 (4x4)
};
__constant__ int c_in[36] = {
    1,1,1,1,1,1,1,1,1,1,1,1,
    1,
    2,2,2,2,2,2,2,2,2,2,2,
    2,
    4,4,4,4,4,4,4,4,4,4,4
};

// ---------------------------------------------------------------------------
// Kernel 1: conv 3x3 SAME, 3->16, one block per image; writes pre-BN y and
// per-block per-channel (sum, sumsq) partials. Fully deterministic.
// ---------------------------------------------------------------------------
__global__ __launch_bounds__(256) void conv_kernel(
    const float* __restrict__ x, const float* __restrict__ cw,
    const float* __restrict__ cb, float* __restrict__ y)
{
    __shared__ float sp[3 * 34 * 34];   // padded image
    __shared__ float wsm[432];          // weights OIHW (16*3*3*3)
    __shared__ float bsm[16];
    __shared__ float red[8][32];

    const int n = blockIdx.x;
    const int tid = threadIdx.x;
    const float* xi = x + (long)n * 3072;

    // FIX (R1 bug): 432 > blockDim, must stride
    for (int i = tid; i < 432; i += 256) wsm[i] = cw[i];
    if (tid < 16)  bsm[tid] = cb[tid];

    // load padded 3x34x34 image
    for (int i = tid; i < 3 * 34 * 34; i += 256) {
        int c = i / 1156, r = i % 1156;
        int yy = r / 34, xx = r % 34;
        float v = 0.0f;
        if (yy >= 1 && yy < 33 && xx >= 1 && xx < 33)
            v = xi[c * 1024 + (yy - 1) * 32 + (xx - 1)];
        sp[i] = v;
    }
    __syncthreads();

    // each thread: 4 pixels x 16 output channels
    float acc[4][16];
    const int p0 = tid;                  // pixels p0, p0+256, p0+512, p0+768
    int hh[4], ww[4];
    #pragma unroll
    for (int k = 0; k < 4; k++) {
        int p = p0 + k * 256;
        hh[k] = p >> 5; ww[k] = p & 31;
        #pragma unroll
        for (int o = 0; o < 16; o++) acc[k][o] = bsm[o];
    }

    #pragma unroll
    for (int c = 0; c < 3; c++) {
        #pragma unroll
        for (int ky = 0; ky < 3; ky++) {
            #pragma unroll
            for (int kx = 0; kx < 3; kx++) {
                float wv[16];
                #pragma unroll
                for (int o = 0; o < 16; o++)
                    wv[o] = wsm[((o * 3 + c) * 3 + ky) * 3 + kx];
                #pragma unroll
                for (int k = 0; k < 4; k++) {
                    float v = sp[c * 1156 + (hh[k] + ky) * 34 + (ww[k] + kx)];
                    #pragma unroll
                    for (int o = 0; o < 16; o++)
                        acc[k][o] += v * wv[o];
                }
            }
        }
    }

    // write pre-BN output + local stats
    float sum[16], sq[16];
    #pragma unroll
    for (int o = 0; o < 16; o++) { sum[o] = 0.0f; sq[o] = 0.0f; }

    float* yout = y + (long)n * 16 * 1024;
    #pragma unroll
    for (int k = 0; k < 4; k++) {
        int p = p0 + k * 256;
        #pragma unroll
        for (int o = 0; o < 16; o++) {
            float v = acc[k][o];
            yout[o * 1024 + p] = v;
            sum[o] += v;
            sq[o]  += v * v;
        }
    }

    // warp reduce 32 values
    #pragma unroll
    for (int o = 0; o < 16; o++) {
        #pragma unroll
        for (int s = 16; s > 0; s >>= 1) {
            sum[o] += __shfl_down_sync(0xffffffffu, sum[o], s);
            sq[o]  += __shfl_down_sync(0xffffffffu, sq[o],  s);
        }
    }
    const int lane = tid & 31, wp = tid >> 5;
    if (lane == 0) {
        #pragma unroll
        for (int o = 0; o < 16; o++) { red[wp][o] = sum[o]; red[wp][16 + o] = sq[o]; }
    }
    __syncthreads();
    if (tid < 32) {
        float t = 0.0f;
        #pragma unroll
        for (int w = 0; w < 8; w++) t += red[w][tid];
        g_partials[blockIdx.x * 32 + tid] = t;
    }
}

// ---------------------------------------------------------------------------
// Kernel 2: reduce 1024 block-partials -> per-channel scale/shift
// ---------------------------------------------------------------------------
__global__ __launch_bounds__(256) void stats_kernel(
    const float* __restrict__ bn_gamma, const float* __restrict__ bn_beta)
{
    __shared__ float red[8][32];
    __shared__ float tot[32];
    const int v  = threadIdx.x & 31;
    const int ck = threadIdx.x >> 5;   // 8 chunks of 128 blocks each
    float s = 0.0f;
    #pragma unroll 8
    for (int b = ck * 128; b < (ck + 1) * 128; b++)
        s += g_partials[b * 32 + v];
    red[ck][v] = s;
    __syncthreads();
    if (threadIdx.x < 32) {
        float t = 0.0f;
        #pragma unroll
        for (int w = 0; w < 8; w++) t += red[w][threadIdx.x];
        tot[threadIdx.x] = t;
    }
    __syncthreads();
    if (threadIdx.x < 16) {
        const float inv_n = 1.0f / N_ELEM_PER_CH;
        float mean = tot[threadIdx.x] * inv_n;
        float var  = tot[16 + threadIdx.x] * inv_n - mean * mean;
        float rstd = rsqrtf(var + 1e-5f);
        float sc   = bn_gamma[threadIdx.x] * rstd;
        g_scale[threadIdx.x] = sc;
        g_shift[threadIdx.x] = bn_beta[threadIdx.x] - mean * sc;
    }
}

// ---------------------------------------------------------------------------
// Kernel 3: in-place normalize + relu (float4, 4.19M vectors)
// ---------------------------------------------------------------------------
__global__ __launch_bounds__(256) void norm_kernel(float* __restrict__ y)
{
    __shared__ float sc[16], sh[16];
    if (threadIdx.x < 16) {
        sc[threadIdx.x] = g_scale[threadIdx.x];
        sh[threadIdx.x] = g_shift[threadIdx.x];
    }
    __syncthreads();
    long i = (long)blockIdx.x * blockDim.x + threadIdx.x;
    const long total = (long)16 * 1024 * 1024 / 4;
    if (i >= total) return;
    float4 v = reinterpret_cast<float4*>(y)[i];
    int c = (int)((i >> 8) & 15);          // (elem/1024)%16, elem = i*4
    float s = sc[c], b = sh[c];
    v.x = fmaxf(v.x * s + b, 0.0f);
    v.y = fmaxf(v.y * s + b, 0.0f);
    v.z = fmaxf(v.z * s + b, 0.0f);
    v.w = fmaxf(v.w * s + b, 0.0f);
    reinterpret_cast<float4*>(y)[i] = v;
}

// ---------------------------------------------------------------------------
// Kernel 4: hypernetwork — one block per z-vector (242 blocks, 256 threads).
// ---------------------------------------------------------------------------
__global__ __launch_bounds__(256) void hyper_kernel(
    const float* __restrict__ z_all,
    const float* __restrict__ w1, const float* __restrict__ b1,
    const float* __restrict__ w2, const float* __restrict__ b2,
    float* __restrict__ out)
{
    __shared__ float zs[64];
    __shared__ float hs[1024];   // h_in [16][64]
    const int n = blockIdx.x, tid = threadIdx.x;

    if (tid < 64) zs[tid] = z_all[n * 64 + tid];
    __syncthreads();

    // phase 1: h_in
    for (int e = tid; e < 1024; e += 256) {
        float a = b2[e];
        #pragma unroll 16
        for (int k = 0; k < 64; k++)
            a += zs[k] * w2[k * 1024 + e];
        hs[e] = a;
    }
    __syncthreads();

    // layer lookup
    int li = 0;
    while (c_offs[li + 1] <= n) li++;
    const int r   = n - c_offs[li];
    const int inn = c_in[li];
    const int o   = r / inn;
    const int ii  = r % inn;
    const long base   = (long)c_offs[li] * 2304 + (long)o * inn * 2304 + (long)ii * 144;
    const int  stride = inn * 144;

    // phase 2: h_fin (9 outputs per thread) + scatter
    const int oo = tid >> 4;          // 0..15
    const int cb = (tid & 15) * 9;    // column base 0,9,...,135
    float acc[9];
    #pragma unroll
    for (int j = 0; j < 9; j++) acc[j] = b1[cb + j];
    #pragma unroll 8
    for (int d = 0; d < 64; d++) {
        float hv = hs[oo * 64 + d];
        const float* w1r = w1 + d * 144 + cb;
        #pragma unroll
        for (int j = 0; j < 9; j++) acc[j] += hv * w1r[j];
    }
    float* op = out + base + (long)oo * stride + cb;
    #pragma unroll
    for (int j = 0; j < 9; j++) op[j] = acc[j];
}

// ---------------------------------------------------------------------------
extern "C" void kernel_launch(void* const* d_in, const int* in_sizes, int n_in,
                              void* d_out, int out_size)
{
    const float* x        = (const float*)d_in[0];
    const float* conv_w   = (const float*)d_in[1];
    const float* conv_b   = (const float*)d_in[2];
    const float* bn_gamma = (const float*)d_in[3];
    const float* bn_beta  = (const float*)d_in[4];
    const float* z_all    = (const float*)d_in[5];
    const float* w1       = (const float*)d_in[6];
    const float* b1       = (const float*)d_in[7];
    const float* w2       = (const float*)d_in[8];
    const float* b2       = (const float*)d_in[9];

    float* out = (float*)d_out;
    float* y   = out + Y_OFFSET;

    // hypernet is independent; issue first so it can slot in
    hyper_kernel<<<242, 256>>>(z_all, w1, b1, w2, b2, out);
    conv_kernel<<<1024, 256>>>(x, conv_w, conv_b, y);
    stats_kernel<<<1, 256>>>(bn_gamma, bn_beta);
    // 16*1024*1024/4 float4 elems = 4194304 -> 16384 blocks of 256
    norm_kernel<<<16384, 256>>>(y);
}

// round 3
// speedup vs baseline: 1.4938x; 1.4938x over previous
#include <cuda_runtime.h>
#include <cuda_bf16.h>

// ---------------------------------------------------------------------------
// Weight_Generation: conv3x3(3->16) + BatchNorm(train) + ReLU on [1024,3,32,32]
// plus hypernetwork generating 36 conv weight tensors from 242 z-vectors.
//
// Output layout (float32): [ 36 weight tensors = 242*2304 floats ][ y : 1024*16*32*32 ]
// ---------------------------------------------------------------------------

#define Y_OFFSET   (242 * 2304)
#define N_ELEM_PER_CH (1024.0f * 1024.0f)

typedef unsigned long long ull;

__device__ float g_partials[1024 * 32];   // [block][ch sum(0..15), ch sumsq(16..31)]
__device__ float g_scale[16];
__device__ float g_shift[16];

__constant__ int c_offs[37] = {
    0,1,2,3,4,5,6,7,8,9,10,11,12,
    14,
    18,22,26,30,34,38,42,46,50,54,58,
    66,
    82,98,114,130,146,162,178,194,210,226,242
};
__constant__ int c_in[36] = {
    1,1,1,1,1,1,1,1,1,1,1,1,
    1,
    2,2,2,2,2,2,2,2,2,2,2,
    2,
    4,4,4,4,4,4,4,4,4,4,4
};

// ---- packed f32x2 helpers (Blackwell dual-fp32 pipe) ----------------------
__device__ __forceinline__ ull pack2(float lo, float hi) {
    ull r; asm("mov.b64 %0, {%1, %2};" : "=l"(r) : "f"(lo), "f"(hi)); return r;
}
__device__ __forceinline__ void unpack2(ull v, float& lo, float& hi) {
    asm("mov.b64 {%0, %1}, %2;" : "=f"(lo), "=f"(hi) : "l"(v));
}
__device__ __forceinline__ ull fma2(ull a, ull b, ull c) {
    ull d; asm("fma.rn.f32x2 %0, %1, %2, %3;" : "=l"(d) : "l"(a), "l"(b), "l"(c)); return d;
}
__device__ __forceinline__ ull add2(ull a, ull b) {
    ull d; asm("add.rn.f32x2 %0, %1, %2;" : "=l"(d) : "l"(a), "l"(b)); return d;
}

// ---------------------------------------------------------------------------
// Fused kernel: blocks [0,1024) = conv; blocks [1024,1266) = hypernet.
// ---------------------------------------------------------------------------
// conv smem layout (bytes):
//   [0, 13872)        sp   : padded image, 3*34*34 floats
//   [13872, 15600)    wts2 : 216 x ull  (transposed weight pairs [27 taps][8 ch-pairs])
//   [15600, 15664)    bp   : 8 x ull    (bias pairs)
//   [15664, 16688)    red  : 8*32 floats
// hyper smem: zs 64 floats, hs 1024 floats (reuses front of buffer)
#define SMEM_BYTES 16688

__global__ __launch_bounds__(256) void fused_conv_hyper(
    const float* __restrict__ x, const float* __restrict__ cw,
    const float* __restrict__ cb, float* __restrict__ y,
    const float* __restrict__ z_all,
    const float* __restrict__ w1, const float* __restrict__ b1,
    const float* __restrict__ w2, const float* __restrict__ b2,
    float* __restrict__ out)
{
    __shared__ __align__(16) char smem_raw[SMEM_BYTES];
    const int tid = threadIdx.x;

    if (blockIdx.x < 1024) {
        // ================= CONV PATH =================
        float* sp   = (float*)smem_raw;
        ull*   wts2 = (ull*)(smem_raw + 13872);
        ull*   bp   = (ull*)(smem_raw + 15600);
        float* red  = (float*)(smem_raw + 15664);

        const int n = blockIdx.x;
        const float* xi = x + (long)n * 3072;

        // transposed weight pairs: wts2[tap*8 + j] = (w[2j], w[2j+1]) at tap (c,ky,kx)
        if (tid < 216) {
            int it = tid >> 3, j = tid & 7;
            int c = it / 9, r9 = it % 9, ky = r9 / 3, kx = r9 % 3;
            int o0 = j * 2;
            float w0 = cw[((o0 * 3 + c) * 3 + ky) * 3 + kx];
            float w1v = cw[(((o0 + 1) * 3 + c) * 3 + ky) * 3 + kx];
            wts2[tid] = pack2(w0, w1v);
        }
        if (tid < 8) bp[tid] = pack2(cb[2 * tid], cb[2 * tid + 1]);

        // padded 3x34x34 image
        for (int i = tid; i < 3 * 34 * 34; i += 256) {
            int c = i / 1156, r = i % 1156;
            int yy = r / 34, xx = r % 34;
            float v = 0.0f;
            if (yy >= 1 && yy < 33 && xx >= 1 && xx < 33)
                v = xi[c * 1024 + (yy - 1) * 32 + (xx - 1)];
            sp[i] = v;
        }
        __syncthreads();

        // 4 pixels per thread (p = tid + k*256), 8 packed channel-pair accs each
        int hh[4], ww[4];
        ull acc[4][8];
        #pragma unroll
        for (int k = 0; k < 4; k++) {
            int p = tid + k * 256;
            hh[k] = p >> 5; ww[k] = p & 31;
            #pragma unroll
            for (int j = 0; j < 8; j++) acc[k][j] = bp[j];
        }

        #pragma unroll
        for (int it = 0; it < 27; ++it) {
            const int c  = it / 9;
            const int ky = (it % 9) / 3;
            const int kx = it % 3;
            ull w[8];
            #pragma unroll
            for (int j = 0; j < 8; j++) w[j] = wts2[it * 8 + j];
            #pragma unroll
            for (int k = 0; k < 4; k++) {
                float v = sp[c * 1156 + (hh[k] + ky) * 34 + (ww[k] + kx)];
                ull vv = pack2(v, v);
                #pragma unroll
                for (int j = 0; j < 8; j++)
                    acc[k][j] = fma2(vv, w[j], acc[k][j]);
            }
        }

        // epilogue: write pre-BN y + packed stats
        ull sum2[8], sq2[8];
        const ull z2 = pack2(0.0f, 0.0f);
        #pragma unroll
        for (int j = 0; j < 8; j++) { sum2[j] = z2; sq2[j] = z2; }

        float* yout = y + (long)n * 16 * 1024;
        #pragma unroll
        for (int k = 0; k < 4; k++) {
            int p = tid + k * 256;
            #pragma unroll
            for (int j = 0; j < 8; j++) {
                float a0, a1;
                unpack2(acc[k][j], a0, a1);
                yout[(2 * j) * 1024 + p]     = a0;
                yout[(2 * j + 1) * 1024 + p] = a1;
                sum2[j] = add2(sum2[j], acc[k][j]);
                sq2[j]  = fma2(acc[k][j], acc[k][j], sq2[j]);
            }
        }

        // unpack to 32 scalars, warp reduce
        float s[16], q[16];
        #pragma unroll
        for (int j = 0; j < 8; j++) {
            unpack2(sum2[j], s[2 * j], s[2 * j + 1]);
            unpack2(sq2[j],  q[2 * j], q[2 * j + 1]);
        }
        #pragma unroll
        for (int o = 0; o < 16; o++) {
            #pragma unroll
            for (int sft = 16; sft > 0; sft >>= 1) {
                s[o] += __shfl_down_sync(0xffffffffu, s[o], sft);
                q[o] += __shfl_down_sync(0xffffffffu, q[o], sft);
            }
        }
        const int lane = tid & 31, wp = tid >> 5;
        if (lane == 0) {
            #pragma unroll
            for (int o = 0; o < 16; o++) {
                red[wp * 32 + o]      = s[o];
                red[wp * 32 + 16 + o] = q[o];
            }
        }
        __syncthreads();
        if (tid < 32) {
            float t = 0.0f;
            #pragma unroll
            for (int w = 0; w < 8; w++) t += red[w * 32 + tid];
            g_partials[n * 32 + tid] = t;
        }
    } else {
        // ================= HYPERNET PATH =================
        float* zs = (float*)smem_raw;
        float* hs = zs + 64;
        const int n = blockIdx.x - 1024;

        if (tid < 64) zs[tid] = z_all[n * 64 + tid];
        __syncthreads();

        for (int e = tid; e < 1024; e += 256) {
            float a = b2[e];
            #pragma unroll 16
            for (int k = 0; k < 64; k++)
                a += zs[k] * w2[k * 1024 + e];
            hs[e] = a;
        }
        __syncthreads();

        int li = 0;
        while (c_offs[li + 1] <= n) li++;
        const int r   = n - c_offs[li];
        const int inn = c_in[li];
        const int o   = r / inn;
        const int ii  = r % inn;
        const long base   = (long)c_offs[li] * 2304 + (long)o * inn * 2304 + (long)ii * 144;
        const int  stride = inn * 144;

        const int oo = tid >> 4;
        const int cbase = (tid & 15) * 9;
        float acc[9];
        #pragma unroll
        for (int j = 0; j < 9; j++) acc[j] = b1[cbase + j];
        #pragma unroll 8
        for (int d = 0; d < 64; d++) {
            float hv = hs[oo * 64 + d];
            const float* w1r = w1 + d * 144 + cbase;
            #pragma unroll
            for (int j = 0; j < 9; j++) acc[j] += hv * w1r[j];
        }
        float* op = out + base + (long)oo * stride + cbase;
        #pragma unroll
        for (int j = 0; j < 9; j++) op[j] = acc[j];
    }
}

// ---------------------------------------------------------------------------
// stats: reduce 1024 block-partials -> per-channel scale/shift
// ---------------------------------------------------------------------------
__global__ __launch_bounds__(256) void stats_kernel(
    const float* __restrict__ bn_gamma, const float* __restrict__ bn_beta)
{
    __shared__ float red[8][32];
    __shared__ float tot[32];
    const int v  = threadIdx.x & 31;
    const int ck = threadIdx.x >> 5;
    float s = 0.0f;
    #pragma unroll 8
    for (int b = ck * 128; b < (ck + 1) * 128; b++)
        s += g_partials[b * 32 + v];
    red[ck][v] = s;
    __syncthreads();
    if (threadIdx.x < 32) {
        float t = 0.0f;
        #pragma unroll
        for (int w = 0; w < 8; w++) t += red[w][threadIdx.x];
        tot[threadIdx.x] = t;
    }
    __syncthreads();
    if (threadIdx.x < 16) {
        const float inv_n = 1.0f / N_ELEM_PER_CH;
        float mean = tot[threadIdx.x] * inv_n;
        float var  = tot[16 + threadIdx.x] * inv_n - mean * mean;
        float rstd = rsqrtf(var + 1e-5f);
        float sc   = bn_gamma[threadIdx.x] * rstd;
        g_scale[threadIdx.x] = sc;
        g_shift[threadIdx.x] = bn_beta[threadIdx.x] - mean * sc;
    }
}

// ---------------------------------------------------------------------------
// norm: in-place normalize + relu, 2 float4 per thread for MLP
// ---------------------------------------------------------------------------
__global__ __launch_bounds__(256) void norm_kernel(float* __restrict__ y)
{
    __shared__ float sc[16], sh[16];
    if (threadIdx.x < 16) {
        sc[threadIdx.x] = g_scale[threadIdx.x];
        sh[threadIdx.x] = g_shift[threadIdx.x];
    }
    __syncthreads();
    const long half = (long)16 * 1024 * 1024 / 8;   // 2097152 float4 per half
    long i0 = (long)blockIdx.x * blockDim.x + threadIdx.x;
    long i1 = i0 + half;
    float4* yv = reinterpret_cast<float4*>(y);

    float4 v0 = yv[i0];
    float4 v1 = yv[i1];
    int c0 = (int)((i0 >> 8) & 15);
    int c1 = (int)((i1 >> 8) & 15);
    float s0 = sc[c0], b0 = sh[c0];
    float s1 = sc[c1], b1v = sh[c1];
    v0.x = fmaxf(v0.x * s0 + b0, 0.0f);
    v0.y = fmaxf(v0.y * s0 + b0, 0.0f);
    v0.z = fmaxf(v0.z * s0 + b0, 0.0f);
    v0.w = fmaxf(v0.w * s0 + b0, 0.0f);
    v1.x = fmaxf(v1.x * s1 + b1v, 0.0f);
    v1.y = fmaxf(v1.y * s1 + b1v, 0.0f);
    v1.z = fmaxf(v1.z * s1 + b1v, 0.0f);
    v1.w = fmaxf(v1.w * s1 + b1v, 0.0f);
    yv[i0] = v0;
    yv[i1] = v1;
}

// ---------------------------------------------------------------------------
extern "C" void kernel_launch(void* const* d_in, const int* in_sizes, int n_in,
                              void* d_out, int out_size)
{
    const float* x        = (const float*)d_in[0];
    const float* conv_w   = (const float*)d_in[1];
    const float* conv_b   = (const float*)d_in[2];
    const float* bn_gamma = (const float*)d_in[3];
    const float* bn_beta  = (const float*)d_in[4];
    const float* z_all    = (const float*)d_in[5];
    const float* w1       = (const float*)d_in[6];
    const float* b1       = (const float*)d_in[7];
    const float* w2       = (const float*)d_in[8];
    const float* b2       = (const float*)d_in[9];

    float* out = (float*)d_out;
    float* y   = out + Y_OFFSET;

    fused_conv_hyper<<<1024 + 242, 256>>>(x, conv_w, conv_b, y,
                                          z_all, w1, b1, w2, b2, out);
    stats_kernel<<<1, 256>>>(bn_gamma, bn_beta);
    // 2097152 threads, 2 float4 each
    norm_kernel<<<8192, 256>>>(y);
}

// round 4
// speedup vs baseline: 1.5002x; 1.0043x over previous
#include <cuda_runtime.h>
#include <cuda_bf16.h>

// ---------------------------------------------------------------------------
// Weight_Generation: conv3x3(3->16) + BatchNorm(train) + ReLU on [1024,3,32,32]
// plus hypernetwork generating 36 conv weight tensors from 242 z-vectors.
//
// Output layout (float32): [ 36 weight tensors = 242*2304 floats ][ y ]
// ---------------------------------------------------------------------------

#define Y_OFFSET   (242 * 2304)
#define N_ELEM_PER_CH (1024.0f * 1024.0f)
#define N_CONV_BLOCKS 2048               // 2 blocks per image (16 rows each)

typedef unsigned long long ull;

__device__ float g_partials[N_CONV_BLOCKS * 32];
__device__ float g_scale[16];
__device__ float g_shift[16];

__constant__ int c_offs[37] = {
    0,1,2,3,4,5,6,7,8,9,10,11,12,
    14,
    18,22,26,30,34,38,42,46,50,54,58,
    66,
    82,98,114,130,146,162,178,194,210,226,242
};
__constant__ int c_in[36] = {
    1,1,1,1,1,1,1,1,1,1,1,1,
    1,
    2,2,2,2,2,2,2,2,2,2,2,
    2,
    4,4,4,4,4,4,4,4,4,4,4
};

// ---- packed f32x2 helpers --------------------------------------------------
__device__ __forceinline__ ull pack2(float lo, float hi) {
    ull r; asm("mov.b64 %0, {%1, %2};" : "=l"(r) : "f"(lo), "f"(hi)); return r;
}
__device__ __forceinline__ void unpack2(ull v, float& lo, float& hi) {
    asm("mov.b64 {%0, %1}, %2;" : "=f"(lo), "=f"(hi) : "l"(v));
}
__device__ __forceinline__ ull fma2(ull a, ull b, ull c) {
    ull d; asm("fma.rn.f32x2 %0, %1, %2, %3;" : "=l"(d) : "l"(a), "l"(b), "l"(c)); return d;
}
__device__ __forceinline__ ull add2(ull a, ull b) {
    ull d; asm("add.rn.f32x2 %0, %1, %2;" : "=l"(d) : "l"(a), "l"(b)); return d;
}

// ---------------------------------------------------------------------------
// Fused kernel: blocks [0,2048) = conv half-image tiles; [2048,2290) = hypernet.
// conv smem: sp2 = duplicated-pair padded tile 3 x 18 x 34 ull (14688 B)
//            wts2 216 ull, bp 8 ull, red 256 f
// ---------------------------------------------------------------------------
#define SP2_CH   612                      // 18*34 ull per channel
#define SMEM_ULL (3*SP2_CH + 216 + 8 + 128)

__global__ __launch_bounds__(256, 4) void fused_conv_hyper(
    const float* __restrict__ x, const float* __restrict__ cw,
    const float* __restrict__ cb, float* __restrict__ y,
    const float* __restrict__ z_all,
    const float* __restrict__ w1, const float* __restrict__ b1,
    const float* __restrict__ w2, const float* __restrict__ b2,
    float* __restrict__ out)
{
    __shared__ __align__(16) ull smem_raw[SMEM_ULL];
    const int tid = threadIdx.x;

    if (blockIdx.x < N_CONV_BLOCKS) {
        // ================= CONV PATH =================
        ull*   sp2  = smem_raw;                      // 3*612
        ull*   wts2 = smem_raw + 3 * SP2_CH;         // 216
        ull*   bp   = wts2 + 216;                    // 8
        float* red  = (float*)(bp + 8);              // 256 floats

        const int n  = blockIdx.x >> 1;
        const int h0 = (blockIdx.x & 1) << 4;        // 0 or 16
        const float* xi = x + (long)n * 3072;

        // transposed weight pairs: wts2[tap*8 + j] = (w[2j],w[2j+1]) at tap(c,ky,kx)
        if (tid < 216) {
            int it = tid >> 3, j = tid & 7;
            int c = it / 9, r9 = it % 9, ky = r9 / 3, kx = r9 % 3;
            int o0 = j * 2;
            wts2[tid] = pack2(cw[((o0 * 3 + c) * 3 + ky) * 3 + kx],
                              cw[(((o0 + 1) * 3 + c) * 3 + ky) * 3 + kx]);
        }
        if (tid < 8) bp[tid] = pack2(cb[2 * tid], cb[2 * tid + 1]);

        // duplicated padded tile: rows h0-1 .. h0+16, cols -1..32
        for (int i = tid; i < 3 * SP2_CH; i += 256) {
            int c = i / SP2_CH, r = i % SP2_CH;
            int yy = r / 34, xx = r % 34;
            int gy = h0 + yy - 1;
            float v = 0.0f;
            if (gy >= 0 && gy < 32 && xx >= 1 && xx < 33)
                v = xi[c * 1024 + gy * 32 + (xx - 1)];
            sp2[i] = pack2(v, v);
        }
        __syncthreads();

        // 2 pixels per thread: p = tid, tid+256 within the 512-pixel half
        const int lr0 = tid >> 5,        c0 = tid & 31;   // local row 0..7
        const int lr1 = lr0 + 8;                          // local row 8..15
        ull acc[2][8];
        #pragma unroll
        for (int j = 0; j < 8; j++) { acc[0][j] = bp[j]; acc[1][j] = bp[j]; }

        #pragma unroll
        for (int it = 0; it < 27; ++it) {
            const int c  = it / 9;
            const int ky = (it % 9) / 3;
            const int kx = it % 3;
            ull w[8];
            #pragma unroll
            for (int j = 0; j < 8; j++) w[j] = wts2[it * 8 + j];
            ull v0 = sp2[c * SP2_CH + (lr0 + ky) * 34 + (c0 + kx)];
            ull v1 = sp2[c * SP2_CH + (lr1 + ky) * 34 + (c0 + kx)];
            #pragma unroll
            for (int j = 0; j < 8; j++) {
                acc[0][j] = fma2(v0, w[j], acc[0][j]);
                acc[1][j] = fma2(v1, w[j], acc[1][j]);
            }
        }

        // epilogue: write pre-BN y + packed stats
        ull sum2[8], sq2[8];
        const ull z2 = pack2(0.0f, 0.0f);
        #pragma unroll
        for (int j = 0; j < 8; j++) { sum2[j] = z2; sq2[j] = z2; }

        float* yout = y + (long)n * 16 * 1024;
        #pragma unroll
        for (int k = 0; k < 2; k++) {
            int pg = (h0 + lr0 + k * 8) * 32 + c0;   // global pixel index
            #pragma unroll
            for (int j = 0; j < 8; j++) {
                float a0, a1;
                unpack2(acc[k][j], a0, a1);
                yout[(2 * j) * 1024 + pg]     = a0;
                yout[(2 * j + 1) * 1024 + pg] = a1;
                sum2[j] = add2(sum2[j], acc[k][j]);
                sq2[j]  = fma2(acc[k][j], acc[k][j], sq2[j]);
            }
        }

        float s[16], q[16];
        #pragma unroll
        for (int j = 0; j < 8; j++) {
            unpack2(sum2[j], s[2 * j], s[2 * j + 1]);
            unpack2(sq2[j],  q[2 * j], q[2 * j + 1]);
        }
        #pragma unroll
        for (int o = 0; o < 16; o++) {
            #pragma unroll
            for (int sft = 16; sft > 0; sft >>= 1) {
                s[o] += __shfl_down_sync(0xffffffffu, s[o], sft);
                q[o] += __shfl_down_sync(0xffffffffu, q[o], sft);
            }
        }
        const int lane = tid & 31, wp = tid >> 5;
        if (lane == 0) {
            #pragma unroll
            for (int o = 0; o < 16; o++) {
                red[wp * 32 + o]      = s[o];
                red[wp * 32 + 16 + o] = q[o];
            }
        }
        __syncthreads();
        if (tid < 32) {
            float t = 0.0f;
            #pragma unroll
            for (int w = 0; w < 8; w++) t += red[w * 32 + tid];
            g_partials[blockIdx.x * 32 + tid] = t;
        }
    } else {
        // ================= HYPERNET PATH =================
        float* zs = (float*)smem_raw;
        float* hs = zs + 64;
        const int n = blockIdx.x - N_CONV_BLOCKS;

        if (tid < 64) zs[tid] = z_all[n * 64 + tid];
        __syncthreads();

        for (int e = tid; e < 1024; e += 256) {
            float a = b2[e];
            #pragma unroll 16
            for (int k = 0; k < 64; k++)
                a += zs[k] * w2[k * 1024 + e];
            hs[e] = a;
        }
        __syncthreads();

        int li = 0;
        while (c_offs[li + 1] <= n) li++;
        const int r   = n - c_offs[li];
        const int inn = c_in[li];
        const int o   = r / inn;
        const int ii  = r % inn;
        const long base   = (long)c_offs[li] * 2304 + (long)o * inn * 2304 + (long)ii * 144;
        const int  stride = inn * 144;

        const int oo = tid >> 4;
        const int cbase = (tid & 15) * 9;
        float acc[9];
        #pragma unroll
        for (int j = 0; j < 9; j++) acc[j] = b1[cbase + j];
        #pragma unroll 8
        for (int d = 0; d < 64; d++) {
            float hv = hs[oo * 64 + d];
            const float* w1r = w1 + d * 144 + cbase;
            #pragma unroll
            for (int j = 0; j < 9; j++) acc[j] += hv * w1r[j];
        }
        float* op = out + base + (long)oo * stride + cbase;
        #pragma unroll
        for (int j = 0; j < 9; j++) op[j] = acc[j];
    }
}

// ---------------------------------------------------------------------------
// stats: reduce 2048 block-partials -> per-channel scale/shift
// ---------------------------------------------------------------------------
__global__ __launch_bounds__(256) void stats_kernel(
    const float* __restrict__ bn_gamma, const float* __restrict__ bn_beta)
{
    __shared__ float red[8][32];
    __shared__ float tot[32];
    const int v  = threadIdx.x & 31;
    const int ck = threadIdx.x >> 5;   // 8 chunks of 256 blocks each
    float s = 0.0f;
    #pragma unroll 8
    for (int b = ck * 256; b < (ck + 1) * 256; b++)
        s += g_partials[b * 32 + v];
    red[ck][v] = s;
    __syncthreads();
    if (threadIdx.x < 32) {
        float t = 0.0f;
        #pragma unroll
        for (int w = 0; w < 8; w++) t += red[w][threadIdx.x];
        tot[threadIdx.x] = t;
    }
    __syncthreads();
    if (threadIdx.x < 16) {
        const float inv_n = 1.0f / N_ELEM_PER_CH;
        float mean = tot[threadIdx.x] * inv_n;
        float var  = tot[16 + threadIdx.x] * inv_n - mean * mean;
        float rstd = rsqrtf(var + 1e-5f);
        float sc   = bn_gamma[threadIdx.x] * rstd;
        g_scale[threadIdx.x] = sc;
        g_shift[threadIdx.x] = bn_beta[threadIdx.x] - mean * sc;
    }
}

// ---------------------------------------------------------------------------
// norm: in-place normalize + relu, 2 float4 per thread
// ---------------------------------------------------------------------------
__global__ __launch_bounds__(256) void norm_kernel(float* __restrict__ y)
{
    __shared__ float sc[16], sh[16];
    if (threadIdx.x < 16) {
        sc[threadIdx.x] = g_scale[threadIdx.x];
        sh[threadIdx.x] = g_shift[threadIdx.x];
    }
    __syncthreads();
    const long half = (long)16 * 1024 * 1024 / 8;
    long i0 = (long)blockIdx.x * blockDim.x + threadIdx.x;
    long i1 = i0 + half;
    float4* yv = reinterpret_cast<float4*>(y);

    float4 v0 = yv[i0];
    float4 v1 = yv[i1];
    int cA = (int)((i0 >> 8) & 15);
    int cB = (int)((i1 >> 8) & 15);
    float s0 = sc[cA], b0 = sh[cA];
    float s1 = sc[cB], b1v = sh[cB];
    v0.x = fmaxf(v0.x * s0 + b0, 0.0f);
    v0.y = fmaxf(v0.y * s0 + b0, 0.0f);
    v0.z = fmaxf(v0.z * s0 + b0, 0.0f);
    v0.w = fmaxf(v0.w * s0 + b0, 0.0f);
    v1.x = fmaxf(v1.x * s1 + b1v, 0.0f);
    v1.y = fmaxf(v1.y * s1 + b1v, 0.0f);
    v1.z = fmaxf(v1.z * s1 + b1v, 0.0f);
    v1.w = fmaxf(v1.w * s1 + b1v, 0.0f);
    yv[i0] = v0;
    yv[i1] = v1;
}

// ---------------------------------------------------------------------------
extern "C" void kernel_launch(void* const* d_in, const int* in_sizes, int n_in,
                              void* d_out, int out_size)
{
    const float* x        = (const float*)d_in[0];
    const float* conv_w   = (const float*)d_in[1];
    const float* conv_b   = (const float*)d_in[2];
    const float* bn_gamma = (const float*)d_in[3];
    const float* bn_beta  = (const float*)d_in[4];
    const float* z_all    = (const float*)d_in[5];
    const float* w1       = (const float*)d_in[6];
    const float* b1       = (const float*)d_in[7];
    const float* w2       = (const float*)d_in[8];
    const float* b2       = (const float*)d_in[9];

    float* out = (float*)d_out;
    float* y   = out + Y_OFFSET;

    fused_conv_hyper<<<N_CONV_BLOCKS + 242, 256>>>(x, conv_w, conv_b, y,
                                                   z_all, w1, b1, w2, b2, out);
    stats_kernel<<<1, 256>>>(bn_gamma, bn_beta);
    norm_kernel<<<8192, 256>>>(y);
}

// round 5
// speedup vs baseline: 1.6639x; 1.1091x over previous
#include <cuda_runtime.h>
#include <cuda_bf16.h>

// ---------------------------------------------------------------------------
// Weight_Generation: conv3x3(3->16) + BatchNorm(train) + ReLU on [1024,3,32,32]
// plus hypernetwork generating 36 conv weight tensors from 242 z-vectors.
// Output layout (float32): [ 36 weight tensors = 242*2304 floats ][ y ]
// ---------------------------------------------------------------------------

#define Y_OFFSET   (242 * 2304)
#define N_ELEM_PER_CH (1024.0f * 1024.0f)
#define N_CONV_BLOCKS 2048               // 2 blocks per image (16 rows each)

typedef unsigned long long ull;

__device__ float g_partials[N_CONV_BLOCKS * 32];
__device__ float g_scale[16];
__device__ float g_shift[16];
__device__ ull   g_stage[224];           // staging for constant upload

// conv weight pairs (216) + bias pairs (8), uploaded each launch via memcpy node
__constant__ ull c_wb[224];

__constant__ int c_offs[37] = {
    0,1,2,3,4,5,6,7,8,9,10,11,12,
    14,
    18,22,26,30,34,38,42,46,50,54,58,
    66,
    82,98,114,130,146,162,178,194,210,226,242
};
__constant__ int c_in[36] = {
    1,1,1,1,1,1,1,1,1,1,1,1,
    1,
    2,2,2,2,2,2,2,2,2,2,2,
    2,
    4,4,4,4,4,4,4,4,4,4,4
};

// ---- packed f32x2 helpers --------------------------------------------------
__device__ __forceinline__ ull pack2(float lo, float hi) {
    ull r; asm("mov.b64 %0, {%1, %2};" : "=l"(r) : "f"(lo), "f"(hi)); return r;
}
__device__ __forceinline__ void unpack2(ull v, float& lo, float& hi) {
    asm("mov.b64 {%0, %1}, %2;" : "=f"(lo), "=f"(hi) : "l"(v));
}
__device__ __forceinline__ ull fma2(ull a, ull b, ull c) {
    ull d; asm("fma.rn.f32x2 %0, %1, %2, %3;" : "=l"(d) : "l"(a), "l"(b), "l"(c)); return d;
}
__device__ __forceinline__ ull add2(ull a, ull b) {
    ull d; asm("add.rn.f32x2 %0, %1, %2;" : "=l"(d) : "l"(a), "l"(b)); return d;
}

// ---------------------------------------------------------------------------
// prep: build transposed (ch-pair) weight/bias pairs in staging buffer
// ---------------------------------------------------------------------------
__global__ void prep_kernel(const float* __restrict__ cw, const float* __restrict__ cb)
{
    int t = threadIdx.x;
    if (t < 216) {
        int it = t >> 3, j = t & 7;
        int c = it / 9, r9 = it % 9, ky = r9 / 3, kx = r9 % 3;
        int o0 = 2 * j;
        g_stage[t] = pack2(cw[((o0 * 3 + c) * 3 + ky) * 3 + kx],
                           cw[(((o0 + 1) * 3 + c) * 3 + ky) * 3 + kx]);
    } else if (t < 224) {
        int j = t - 216;
        g_stage[t] = pack2(cb[2 * j], cb[2 * j + 1]);
    }
}

// ---------------------------------------------------------------------------
// Fused kernel: blocks [0,2048) = conv half-image tiles; [2048,2290) = hypernet.
// conv smem: sp2 duplicated-pair padded tile 3 x 18 x 34 ull + red2 32x32 f
// ---------------------------------------------------------------------------
#define SP2_CH   612                      // 18*34 ull per channel
#define SMEM_ULL (3*SP2_CH + 512)         // + 32*32 floats

__global__ __launch_bounds__(256, 5) void fused_conv_hyper(
    const float* __restrict__ x, float* __restrict__ y,
    const float* __restrict__ z_all,
    const float* __restrict__ w1, const float* __restrict__ b1,
    const float* __restrict__ w2, const float* __restrict__ b2,
    float* __restrict__ out)
{
    __shared__ __align__(16) ull smem_raw[SMEM_ULL];
    const int tid = threadIdx.x;

    if (blockIdx.x < N_CONV_BLOCKS) {
        // ================= CONV PATH =================
        ull*   sp2  = smem_raw;                        // 3*612
        float* red2 = (float*)(smem_raw + 3 * SP2_CH); // 1024 floats

        const int n  = blockIdx.x >> 1;
        const int h0 = (blockIdx.x & 1) << 4;          // 0 or 16
        const float* xi = x + (long)n * 3072;

        // duplicated padded tile: rows h0-1 .. h0+16, cols -1..32
        for (int i = tid; i < 3 * SP2_CH; i += 256) {
            int c = i / SP2_CH, r = i % SP2_CH;
            int yy = r / 34, xx = r % 34;
            int gy = h0 + yy - 1;
            float v = 0.0f;
            if (gy >= 0 && gy < 32 && xx >= 1 && xx < 33)
                v = xi[c * 1024 + gy * 32 + (xx - 1)];
            sp2[i] = pack2(v, v);
        }
        __syncthreads();

        // 2 pixels per thread: local rows lr0, lr0+8, col c0
        const int lr0 = tid >> 5, c0 = tid & 31;
        const int lr1 = lr0 + 8;
        ull acc[2][8];
        #pragma unroll
        for (int j = 0; j < 8; j++) { acc[0][j] = c_wb[216 + j]; acc[1][j] = c_wb[216 + j]; }

        #pragma unroll
        for (int it = 0; it < 27; ++it) {
            const int c  = it / 9;
            const int ky = (it % 9) / 3;
            const int kx = it % 3;
            ull v0 = sp2[c * SP2_CH + (lr0 + ky) * 34 + (c0 + kx)];
            ull v1 = sp2[c * SP2_CH + (lr1 + ky) * 34 + (c0 + kx)];
            #pragma unroll
            for (int j = 0; j < 8; j++) {
                const ull w = c_wb[it * 8 + j];      // constant port (LDCU), imm offset
                acc[0][j] = fma2(v0, w, acc[0][j]);
                acc[1][j] = fma2(v1, w, acc[1][j]);
            }
        }

        // epilogue: write pre-BN y + packed stats
        ull sum2[8], sq2[8];
        const ull z2 = pack2(0.0f, 0.0f);
        #pragma unroll
        for (int j = 0; j < 8; j++) { sum2[j] = z2; sq2[j] = z2; }

        float* yout = y + (long)n * 16 * 1024;
        #pragma unroll
        for (int k = 0; k < 2; k++) {
            int pg = (h0 + lr0 + k * 8) * 32 + c0;
            #pragma unroll
            for (int j = 0; j < 8; j++) {
                float a0, a1;
                unpack2(acc[k][j], a0, a1);
                yout[(2 * j) * 1024 + pg]     = a0;
                yout[(2 * j + 1) * 1024 + pg] = a1;
                sum2[j] = add2(sum2[j], acc[k][j]);
                sq2[j]  = fma2(acc[k][j], acc[k][j], sq2[j]);
            }
        }

        float s[16], q[16];
        #pragma unroll
        for (int j = 0; j < 8; j++) {
            unpack2(sum2[j], s[2 * j], s[2 * j + 1]);
            unpack2(sq2[j],  q[2 * j], q[2 * j + 1]);
        }
        // 3-step shuffle: lanes 0..3 hold partials over lanes == lane (mod 4)
        #pragma unroll
        for (int o = 0; o < 16; o++) {
            #pragma unroll
            for (int sft = 16; sft >= 4; sft >>= 1) {
                s[o] += __shfl_down_sync(0xffffffffu, s[o], sft);
                q[o] += __shfl_down_sync(0xffffffffu, q[o], sft);
            }
        }
        const int lane = tid & 31, wp = tid >> 5;
        if (lane < 4) {
            float* rr = red2 + (wp * 4 + lane) * 32;
            #pragma unroll
            for (int o = 0; o < 16; o++) { rr[o] = s[o]; rr[16 + o] = q[o]; }
        }
        __syncthreads();
        if (tid < 32) {
            float t = 0.0f;
            #pragma unroll
            for (int g = 0; g < 32; g++) t += red2[g * 32 + tid];
            g_partials[blockIdx.x * 32 + tid] = t;
        }
    } else {
        // ================= HYPERNET PATH =================
        float* zs = (float*)smem_raw;
        float* hs = zs + 64;
        const int n = blockIdx.x - N_CONV_BLOCKS;

        if (tid < 64) zs[tid] = z_all[n * 64 + tid];
        __syncthreads();

        for (int e = tid; e < 1024; e += 256) {
            float a = b2[e];
            #pragma unroll 16
            for (int k = 0; k < 64; k++)
                a += zs[k] * w2[k * 1024 + e];
            hs[e] = a;
        }
        __syncthreads();

        int li = 0;
        while (c_offs[li + 1] <= n) li++;
        const int r   = n - c_offs[li];
        const int inn = c_in[li];
        const int o   = r / inn;
        const int ii  = r % inn;
        const long base   = (long)c_offs[li] * 2304 + (long)o * inn * 2304 + (long)ii * 144;
        const int  stride = inn * 144;

        const int oo = tid >> 4;
        const int cbase = (tid & 15) * 9;
        float acc[9];
        #pragma unroll
        for (int j = 0; j < 9; j++) acc[j] = b1[cbase + j];
        #pragma unroll 8
        for (int d = 0; d < 64; d++) {
            float hv = hs[oo * 64 + d];
            const float* w1r = w1 + d * 144 + cbase;
            #pragma unroll
            for (int j = 0; j < 9; j++) acc[j] += hv * w1r[j];
        }
        float* op = out + base + (long)oo * stride + cbase;
        #pragma unroll
        for (int j = 0; j < 9; j++) op[j] = acc[j];
    }
}

// ---------------------------------------------------------------------------
// stats: reduce 2048 block-partials -> per-channel scale/shift
// ---------------------------------------------------------------------------
__global__ __launch_bounds__(256) void stats_kernel(
    const float* __restrict__ bn_gamma, const float* __restrict__ bn_beta)
{
    __shared__ float red[8][32];
    __shared__ float tot[32];
    const int v  = threadIdx.x & 31;
    const int ck = threadIdx.x >> 5;
    float s = 0.0f;
    #pragma unroll 8
    for (int b = ck * 256; b < (ck + 1) * 256; b++)
        s += g_partials[b * 32 + v];
    red[ck][v] = s;
    __syncthreads();
    if (threadIdx.x < 32) {
        float t = 0.0f;
        #pragma unroll
        for (int w = 0; w < 8; w++) t += red[w][threadIdx.x];
        tot[threadIdx.x] = t;
    }
    __syncthreads();
    if (threadIdx.x < 16) {
        const float inv_n = 1.0f / N_ELEM_PER_CH;
        float mean = tot[threadIdx.x] * inv_n;
        float var  = tot[16 + threadIdx.x] * inv_n - mean * mean;
        float rstd = rsqrtf(var + 1e-5f);
        float sc   = bn_gamma[threadIdx.x] * rstd;
        g_scale[threadIdx.x] = sc;
        g_shift[threadIdx.x] = bn_beta[threadIdx.x] - mean * sc;
    }
}

// ---------------------------------------------------------------------------
// norm: in-place normalize + relu, 2 float4 per thread
// ---------------------------------------------------------------------------
__global__ __launch_bounds__(256) void norm_kernel(float* __restrict__ y)
{
    __shared__ float sc[16], sh[16];
    if (threadIdx.x < 16) {
        sc[threadIdx.x] = g_scale[threadIdx.x];
        sh[threadIdx.x] = g_shift[threadIdx.x];
    }
    __syncthreads();
    const long half = (long)16 * 1024 * 1024 / 8;
    long i0 = (long)blockIdx.x * blockDim.x + threadIdx.x;
    long i1 = i0 + half;
    float4* yv = reinterpret_cast<float4*>(y);

    float4 v0 = yv[i0];
    float4 v1 = yv[i1];
    int cA = (int)((i0 >> 8) & 15);
    int cB = (int)((i1 >> 8) & 15);
    float s0 = sc[cA], b0 = sh[cA];
    float s1 = sc[cB], b1v = sh[cB];
    v0.x = fmaxf(v0.x * s0 + b0, 0.0f);
    v0.y = fmaxf(v0.y * s0 + b0, 0.0f);
    v0.z = fmaxf(v0.z * s0 + b0, 0.0f);
    v0.w = fmaxf(v0.w * s0 + b0, 0.0f);
    v1.x = fmaxf(v1.x * s1 + b1v, 0.0f);
    v1.y = fmaxf(v1.y * s1 + b1v, 0.0f);
    v1.z = fmaxf(v1.z * s1 + b1v, 0.0f);
    v1.w = fmaxf(v1.w * s1 + b1v, 0.0f);
    yv[i0] = v0;
    yv[i1] = v1;
}

// ---------------------------------------------------------------------------
extern "C" void kernel_launch(void* const* d_in, const int* in_sizes, int n_in,
                              void* d_out, int out_size)
{
    const float* x        = (const float*)d_in[0];
    const float* conv_w   = (const float*)d_in[1];
    const float* conv_b   = (const float*)d_in[2];
    const float* bn_gamma = (const float*)d_in[3];
    const float* bn_beta  = (const float*)d_in[4];
    const float* z_all    = (const float*)d_in[5];
    const float* w1       = (const float*)d_in[6];
    const float* b1       = (const float*)d_in[7];
    const float* w2       = (const float*)d_in[8];
    const float* b2       = (const float*)d_in[9];

    float* out = (float*)d_out;
    float* y   = out + Y_OFFSET;

    // build packed weight/bias pairs, then upload to __constant__ (D2D memcpy node)
    prep_kernel<<<1, 224>>>(conv_w, conv_b);
    void* stage_addr = nullptr;
    cudaGetSymbolAddress(&stage_addr, g_stage);
    cudaMemcpyToSymbolAsync(c_wb, stage_addr, 224 * sizeof(ull), 0,
                            cudaMemcpyDeviceToDevice, 0);

    fused_conv_hyper<<<N_CONV_BLOCKS + 242, 256>>>(x, y, z_all, w1, b1, w2, b2, out);
    stats_kernel<<<1, 256>>>(bn_gamma, bn_beta);
    norm_kernel<<<8192, 256>>>(y);
}